// round 12
// baseline (speedup 1.0000x reference)
#include <cuda_runtime.h>
#include <cuda_bf16.h>
#include <cstdint>

#define ULL unsigned long long

// ---------------------------------------------------------------------------
// Packed f32x2 helpers.
// ---------------------------------------------------------------------------
__device__ __forceinline__ ULL dup2(float v) {
    ULL r; asm("mov.b64 %0, {%1, %1};" : "=l"(r) : "f"(v)); return r;
}
__device__ __forceinline__ ULL pk2(float lo, float hi) {
    ULL r; asm("mov.b64 %0, {%1, %2};" : "=l"(r) : "f"(lo), "f"(hi)); return r;
}
__device__ __forceinline__ void fma2(ULL& d, ULL a, ULL b) {
    asm("fma.rn.f32x2 %0, %1, %2, %0;" : "+l"(d) : "l"(a), "l"(b));
}
__device__ __forceinline__ void add2(ULL& d, ULL a) {
    asm("add.rn.f32x2 %0, %0, %1;" : "+l"(d) : "l"(a));
}
__device__ __forceinline__ void unpk(ULL v, float& lo, float& hi) {
    asm("mov.b64 {%0, %1}, %2;" : "=f"(lo), "=f"(hi) : "l"(v));
}
__device__ __forceinline__ ULL shflx(ULL v, int m) {
    return __shfl_xor_sync(0xffffffffu, v, m);
}

__device__ __forceinline__ float sig_f(float x) {
    return __fdividef(1.0f, 1.0f + __expf(-x));
}
__device__ __forceinline__ float tanh_f(float x) {
    return __fdividef(2.0f, 1.0f + __expf(-2.0f * x)) - 1.0f;
}

// ---------------------------------------------------------------------------
// Problem constants
// ---------------------------------------------------------------------------
static constexpr int B = 1024;
static constexpr int T = 512;

// Scratch (allocation-free per harness rules)
__device__ float g_y0[(size_t)B * T * 128];   // layer-0 output [b][t][dir*64+k]
__device__ float g_hcat[(size_t)B * 128];     // final hidden [hT_f, hT_b]

// Activation-row stride in ULLs
static constexpr int AS = 18;

// ---------------------------------------------------------------------------
// Shared shuffle-reduction: 4 K-quarters live in lane bits 0-1.
// Input: A0/A1[8] partials (8 local rows). Output: B0/B1[2] full sums for
// local rows 2kq, 2kq+1. Branchless kq-predicated selects; 2-stage butterfly.
// ---------------------------------------------------------------------------
__device__ __forceinline__ void kred(const ULL* A0, const ULL* A1,
                                     int k1, int k0, ULL* B0, ULL* B1)
{
    ULL K0[4], K1[4];
    #pragma unroll
    for (int i = 0; i < 4; i++) {
        ULL s0 = k1 ? A0[i] : A0[4 + i];
        ULL s1 = k1 ? A1[i] : A1[4 + i];
        ULL r0 = shflx(s0, 2);
        ULL r1 = shflx(s1, 2);
        K0[i] = k1 ? A0[4 + i] : A0[i];  add2(K0[i], r0);
        K1[i] = k1 ? A1[4 + i] : A1[i];  add2(K1[i], r1);
    }
    #pragma unroll
    for (int i = 0; i < 2; i++) {
        ULL s0 = k0 ? K0[i] : K0[2 + i];
        ULL s1 = k0 ? K1[i] : K1[2 + i];
        ULL r0 = shflx(s0, 1);
        ULL r1 = shflx(s1, 1);
        B0[i] = k0 ? K0[2 + i] : K0[i];  add2(B0[i], r0);
        B1[i] = k0 ? K1[2 + i] : K1[i];  add2(B1[i], r1);
    }
}

// ---------------------------------------------------------------------------
// Kernel 1: layer-0 bidirectional LSTM, K-split x4.
// block=512: tid = pg*256 + jj*4 + kq. Thread computes partials over
// kk in [kq*16, kq*16+16) for 8 rows (group pg), 4 gates of unit jj;
// shuffle-reduces across kq; finishes rows 8pg+2kq, +1.
// grid=(B/16, 2 dirs) = 128 CTAs.
// ---------------------------------------------------------------------------
static constexpr int SMEM0 = 64 * 256 * 4 + 64 * AS * 8;   // 74752

__global__ void __launch_bounds__(512, 1) lstm0_kernel(
    const float* __restrict__ x,
    const float* __restrict__ WihF, const float* __restrict__ WhhF,
    const float* __restrict__ bihF, const float* __restrict__ bhhF,
    const float* __restrict__ WihB, const float* __restrict__ WhhB,
    const float* __restrict__ bihB, const float* __restrict__ bhhB)
{
    extern __shared__ float sm[];
    float* wt  = sm;                       // [64][256]
    ULL*   h_s = (ULL*)(sm + 64 * 256);    // [64][AS]

    const int dir = blockIdx.y;
    const int b0  = blockIdx.x * 16;
    const int tid = threadIdx.x;
    const int kq  = tid & 3;
    const int jj  = (tid >> 2) & 63;
    const int pg  = tid >> 8;
    const int k1  = (kq >> 1) & 1;
    const int k0  = kq & 1;

    const float* Wih = dir ? WihB : WihF;
    const float* Whh = dir ? WhhB : WhhF;
    const float* bih = dir ? bihB : bihF;
    const float* bhh = dir ? bhhB : bhhF;

    // stage Whh transposed: wt[kk][j*4+g]
    for (int sidx = tid; sidx < 256 * 64; sidx += 512) {
        int gr = sidx >> 6, kk = sidx & 63;
        wt[kk * 256 + (gr & 63) * 4 + (gr >> 6)] = Whh[sidx];
    }
    ULL wA[3], wB[3];
    #pragma unroll
    for (int c = 0; c < 3; c++) {
        wA[c] = pk2(Wih[jj * 3 + c],         Wih[(64 + jj) * 3 + c]);
        wB[c] = pk2(Wih[(128 + jj) * 3 + c], Wih[(192 + jj) * 3 + c]);
    }
    const ULL biasA = pk2(bih[jj] + bhh[jj],             bih[64 + jj] + bhh[64 + jj]);
    const ULL biasB = pk2(bih[128 + jj] + bhh[128 + jj], bih[192 + jj] + bhh[192 + jj]);

    for (int idx = tid; idx < 64 * AS; idx += 512) h_s[idx] = 0ULL;

    // finishing rows: 8*pg + 2*kq + i
    const float* xr[2];
    float*       yr[2];
    const int dof = dir ? 64 : 0;
    #pragma unroll
    for (int i = 0; i < 2; i++) {
        int row = 8 * pg + 2 * kq + i;
        xr[i] = x + (size_t)(b0 + row) * 1536;
        yr[i] = g_y0 + (size_t)(b0 + row) * (T * 128) + dof + jj;
    }

    float cs[2] = {0.f, 0.f};
    float hh[2] = {0.f, 0.f};
    const ULL* hp = h_s + pg * 8;
    const int kb = kq * 16;
    __syncthreads();

    for (int s = 0; s < T; s++) {
        const int t = dir ? (T - 1 - s) : s;

        float xv[2][3];
        #pragma unroll
        for (int i = 0; i < 2; i++) {
            xv[i][0] = __ldg(xr[i] + t);
            xv[i][1] = __ldg(xr[i] + 512 + t);
            xv[i][2] = __ldg(xr[i] + 1024 + t);
        }

        ULL A0[8], A1[8];
        #pragma unroll
        for (int r = 0; r < 8; r++) {
            bool own = (r >> 1) == kq;
            A0[r] = own ? biasA : 0ULL;
            A1[r] = own ? biasB : 0ULL;
        }

        #pragma unroll 8
        for (int kk2 = 0; kk2 < 16; kk2++) {
            int kk = kb + kk2;
            ulonglong2 w2  = *(const ulonglong2*)(wt + kk * 256 + jj * 4);
            ulonglong2 hv0 = *(const ulonglong2*)(hp + kk * AS);
            ulonglong2 hv1 = *(const ulonglong2*)(hp + kk * AS + 2);
            ulonglong2 hv2 = *(const ulonglong2*)(hp + kk * AS + 4);
            ulonglong2 hv3 = *(const ulonglong2*)(hp + kk * AS + 6);
            fma2(A0[0], w2.x, hv0.x);  fma2(A1[0], w2.y, hv0.x);
            fma2(A0[1], w2.x, hv0.y);  fma2(A1[1], w2.y, hv0.y);
            fma2(A0[2], w2.x, hv1.x);  fma2(A1[2], w2.y, hv1.x);
            fma2(A0[3], w2.x, hv1.y);  fma2(A1[3], w2.y, hv1.y);
            fma2(A0[4], w2.x, hv2.x);  fma2(A1[4], w2.y, hv2.x);
            fma2(A0[5], w2.x, hv2.y);  fma2(A1[5], w2.y, hv2.y);
            fma2(A0[6], w2.x, hv3.x);  fma2(A1[6], w2.y, hv3.x);
            fma2(A0[7], w2.x, hv3.y);  fma2(A1[7], w2.y, hv3.y);
        }
        __syncthreads();   // B: all h_s reads done

        // shuffle reduction across kq
        ULL B0[2], B1[2];
        kred(A0, A1, k1, k0, B0, B1);

        // finish: x terms + activations + state update for 2 rows
        #pragma unroll
        for (int i = 0; i < 2; i++) {
            #pragma unroll
            for (int c = 0; c < 3; c++) {
                ULL xd = dup2(xv[i][c]);
                fma2(B0[i], wA[c], xd);
                fma2(B1[i], wB[c], xd);
            }
            float ai, af, ag, ao;
            unpk(B0[i], ai, af);
            unpk(B1[i], ag, ao);
            cs[i] = sig_f(af) * cs[i] + sig_f(ai) * tanh_f(ag);
            hh[i] = sig_f(ao) * tanh_f(cs[i]);
            yr[i][(size_t)t * 128] = hh[i];
        }

        // publish h (dup-packed) for next step
        *(ulonglong2*)(h_s + jj * AS + pg * 8 + 2 * kq)
            = make_ulonglong2(dup2(hh[0]), dup2(hh[1]));
        __syncthreads();   // D: h(t+1) visible
    }
}

// ---------------------------------------------------------------------------
// Kernel 2: layer-1 bidirectional LSTM, input GEMM fused, K-split x4.
// Combined activation buffer act[0..127]=y0(t) dup'd, act[128..191]=h dup'd;
// combined weight panel wt[0..127]=Wih1^T, wt[128..191]=Whh1^T.
// kq covers kk in [kq*48, kq*48+48). grid=(B/16, 2) = 128 CTAs.
// ---------------------------------------------------------------------------
static constexpr int SMEM1 = 192 * 256 * 4 + 192 * AS * 8;  // 224256

__global__ void __launch_bounds__(512, 1) lstm1_kernel(
    const float* __restrict__ WihF, const float* __restrict__ WhhF,
    const float* __restrict__ bihF, const float* __restrict__ bhhF,
    const float* __restrict__ WihB, const float* __restrict__ WhhB,
    const float* __restrict__ bihB, const float* __restrict__ bhhB)
{
    extern __shared__ float sm[];
    float* wt  = sm;                          // [192][256]
    ULL*   act = (ULL*)(sm + 192 * 256);      // [192][AS]: y then h
    ULL*   h_s = act + 128 * AS;

    const int dir = blockIdx.y;
    const int b0  = blockIdx.x * 16;
    const int tid = threadIdx.x;
    const int kq  = tid & 3;
    const int jj  = (tid >> 2) & 63;
    const int pg  = tid >> 8;
    const int k1  = (kq >> 1) & 1;
    const int k0  = kq & 1;

    const float* Wih = dir ? WihB : WihF;
    const float* Whh = dir ? WhhB : WhhF;
    const float* bih = dir ? bihB : bihF;
    const float* bhh = dir ? bhhB : bhhF;

    for (int sidx = tid; sidx < 256 * 128; sidx += 512) {
        int gr = sidx >> 7, kk = sidx & 127;
        wt[kk * 256 + (gr & 63) * 4 + (gr >> 6)] = Wih[sidx];
    }
    for (int sidx = tid; sidx < 256 * 64; sidx += 512) {
        int gr = sidx >> 6, kk = sidx & 63;
        wt[(128 + kk) * 256 + (gr & 63) * 4 + (gr >> 6)] = Whh[sidx];
    }
    const ULL biasA = pk2(bih[jj] + bhh[jj],             bih[64 + jj] + bhh[64 + jj]);
    const ULL biasB = pk2(bih[128 + jj] + bhh[128 + jj], bih[192 + jj] + bhh[192 + jj]);

    for (int idx = tid; idx < 64 * AS; idx += 512) h_s[idx] = 0ULL;

    // y-fill role: row frow = tid>>5 (0..15), feats (tid&31) + 32*i, i<4
    const int frow = tid >> 5;
    const int flo  = tid & 31;
    const float* ybase = g_y0 + (size_t)(b0 + frow) * (T * 128) + flo;

    float cs[2] = {0.f, 0.f};
    float hh[2] = {0.f, 0.f};
    const ULL* ap = act + pg * 8;
    const int kb = kq * 48;
    const int dof = dir ? 64 : 0;

    // prefetch first step's y0
    float p[4];
    {
        int t0 = dir ? T - 1 : 0;
        #pragma unroll
        for (int i = 0; i < 4; i++)
            p[i] = ybase[(size_t)t0 * 128 + 32 * i];
    }
    __syncthreads();

    for (int s = 0; s < T; s++) {
        // publish this step's y0 (dup-packed) into act[0..127]
        #pragma unroll
        for (int i = 0; i < 4; i++)
            act[(32 * i + flo) * AS + frow] = dup2(p[i]);
        __syncthreads();   // A: y + h visible

        // prefetch next step's y0 (hidden under the K-loop)
        if (s + 1 < T) {
            int tn = dir ? (T - 2 - s) : (s + 1);
            #pragma unroll
            for (int i = 0; i < 4; i++)
                p[i] = ybase[(size_t)tn * 128 + 32 * i];
        }

        ULL A0[8], A1[8];
        #pragma unroll
        for (int r = 0; r < 8; r++) {
            bool own = (r >> 1) == kq;
            A0[r] = own ? biasA : 0ULL;
            A1[r] = own ? biasB : 0ULL;
        }

        #pragma unroll 8
        for (int kk2 = 0; kk2 < 48; kk2++) {
            int kk = kb + kk2;
            ulonglong2 w2  = *(const ulonglong2*)(wt + kk * 256 + jj * 4);
            ulonglong2 av0 = *(const ulonglong2*)(ap + kk * AS);
            ulonglong2 av1 = *(const ulonglong2*)(ap + kk * AS + 2);
            ulonglong2 av2 = *(const ulonglong2*)(ap + kk * AS + 4);
            ulonglong2 av3 = *(const ulonglong2*)(ap + kk * AS + 6);
            fma2(A0[0], w2.x, av0.x);  fma2(A1[0], w2.y, av0.x);
            fma2(A0[1], w2.x, av0.y);  fma2(A1[1], w2.y, av0.y);
            fma2(A0[2], w2.x, av1.x);  fma2(A1[2], w2.y, av1.x);
            fma2(A0[3], w2.x, av1.y);  fma2(A1[3], w2.y, av1.y);
            fma2(A0[4], w2.x, av2.x);  fma2(A1[4], w2.y, av2.x);
            fma2(A0[5], w2.x, av2.y);  fma2(A1[5], w2.y, av2.y);
            fma2(A0[6], w2.x, av3.x);  fma2(A1[6], w2.y, av3.x);
            fma2(A0[7], w2.x, av3.y);  fma2(A1[7], w2.y, av3.y);
        }
        __syncthreads();   // B: all act reads done

        ULL B0[2], B1[2];
        kred(A0, A1, k1, k0, B0, B1);

        #pragma unroll
        for (int i = 0; i < 2; i++) {
            float ai, af, ag, ao;
            unpk(B0[i], ai, af);
            unpk(B1[i], ag, ao);
            cs[i] = sig_f(af) * cs[i] + sig_f(ai) * tanh_f(ag);
            hh[i] = sig_f(ao) * tanh_f(cs[i]);
        }

        // publish h (dup-packed); next iter's A-barrier makes it visible
        *(ulonglong2*)(h_s + jj * AS + pg * 8 + 2 * kq)
            = make_ulonglong2(dup2(hh[0]), dup2(hh[1]));
    }

    #pragma unroll
    for (int i = 0; i < 2; i++) {
        int row = 8 * pg + 2 * kq + i;
        g_hcat[(size_t)(b0 + row) * 128 + dof + jj] = hh[i];
    }
}

// ---------------------------------------------------------------------------
// Kernel 3: FC head. block = 256 = 4 rows x 64 fc1-outputs, grid = B/4.
// ---------------------------------------------------------------------------
__global__ void __launch_bounds__(256) head_kernel(
    const float* __restrict__ fc1W, const float* __restrict__ fc1b,
    const float* __restrict__ fc2W, const float* __restrict__ fc2b,
    float* __restrict__ out)
{
    __shared__ float f1[4][64];
    const int j = threadIdx.x;
    const int r = j >> 6;
    const int o = j & 63;
    const int b = blockIdx.x * 4 + r;

    const float* h = g_hcat + (size_t)b * 128;
    const float* w = fc1W + o * 128;
    float acc = fc1b[o];
    #pragma unroll 8
    for (int kk = 0; kk < 128; kk++) acc += w[kk] * h[kk];
    f1[r][o] = fmaxf(acc, 0.0f);
    __syncthreads();

    if (o < 2) {
        float a = fc2b[o];
        const float* w2 = fc2W + o * 64;
        #pragma unroll 8
        for (int kk = 0; kk < 64; kk++) a += w2[kk] * f1[r][kk];
        out[(size_t)b * 2 + o] = a;
    }
}

// ---------------------------------------------------------------------------
// Launcher
// ---------------------------------------------------------------------------
extern "C" void kernel_launch(void* const* d_in, const int* in_sizes, int n_in,
                              void* d_out, int out_size)
{
    const float* x      = (const float*)d_in[0];
    const float* Wih0f  = (const float*)d_in[1];
    const float* Whh0f  = (const float*)d_in[2];
    const float* bih0f  = (const float*)d_in[3];
    const float* bhh0f  = (const float*)d_in[4];
    const float* Wih0b  = (const float*)d_in[5];
    const float* Whh0b  = (const float*)d_in[6];
    const float* bih0b  = (const float*)d_in[7];
    const float* bhh0b  = (const float*)d_in[8];
    const float* Wih1f  = (const float*)d_in[9];
    const float* Whh1f  = (const float*)d_in[10];
    const float* bih1f  = (const float*)d_in[11];
    const float* bhh1f  = (const float*)d_in[12];
    const float* Wih1b  = (const float*)d_in[13];
    const float* Whh1b  = (const float*)d_in[14];
    const float* bih1b  = (const float*)d_in[15];
    const float* bhh1b  = (const float*)d_in[16];
    const float* fc1W   = (const float*)d_in[17];
    const float* fc1b   = (const float*)d_in[18];
    const float* fc2W   = (const float*)d_in[19];
    const float* fc2b   = (const float*)d_in[20];
    float* out = (float*)d_out;

    cudaFuncSetAttribute(lstm0_kernel,
                         cudaFuncAttributeMaxDynamicSharedMemorySize, SMEM0);
    cudaFuncSetAttribute(lstm1_kernel,
                         cudaFuncAttributeMaxDynamicSharedMemorySize, SMEM1);

    dim3 grid(B / 16, 2);
    lstm0_kernel<<<grid, 512, SMEM0>>>(x,
                                       Wih0f, Whh0f, bih0f, bhh0f,
                                       Wih0b, Whh0b, bih0b, bhh0b);

    lstm1_kernel<<<grid, 512, SMEM1>>>(Wih1f, Whh1f, bih1f, bhh1f,
                                       Wih1b, Whh1b, bih1b, bhh1b);

    head_kernel<<<B / 4, 256>>>(fc1W, fc1b, fc2W, fc2b, out);
}

// round 13
// speedup vs baseline: 4.8037x; 4.8037x over previous
#include <cuda_runtime.h>
#include <cuda_bf16.h>
#include <cstdint>

#define ULL unsigned long long

// ---------------------------------------------------------------------------
// Packed f32x2 helpers.
// ---------------------------------------------------------------------------
__device__ __forceinline__ ULL dup2(float v) {
    ULL r; asm("mov.b64 %0, {%1, %1};" : "=l"(r) : "f"(v)); return r;
}
__device__ __forceinline__ ULL pk2(float lo, float hi) {
    ULL r; asm("mov.b64 %0, {%1, %2};" : "=l"(r) : "f"(lo), "f"(hi)); return r;
}
__device__ __forceinline__ void fma2(ULL& d, ULL a, ULL b) {
    asm("fma.rn.f32x2 %0, %1, %2, %0;" : "+l"(d) : "l"(a), "l"(b));
}
__device__ __forceinline__ void add2(ULL& d, ULL a) {
    asm("add.rn.f32x2 %0, %0, %1;" : "+l"(d) : "l"(a));
}
__device__ __forceinline__ void unpk(ULL v, float& lo, float& hi) {
    asm("mov.b64 {%0, %1}, %2;" : "=f"(lo), "=f"(hi) : "l"(v));
}

__device__ __forceinline__ float sig_f(float x) {
    return __fdividef(1.0f, 1.0f + __expf(-x));
}
__device__ __forceinline__ float tanh_f(float x) {
    return __fdividef(2.0f, 1.0f + __expf(-2.0f * x)) - 1.0f;
}

// ---------------------------------------------------------------------------
// Problem constants
// ---------------------------------------------------------------------------
static constexpr int B = 1024;
static constexpr int T = 512;

// Scratch (allocation-free per harness rules)
__device__ float g_y0[(size_t)B * T * 128];   // layer-0 output [b][t][dir*64+k]
__device__ float g_hcat[(size_t)B * 128];     // final hidden [hT_f, hT_b]

// Activation-row stride in ULLs
static constexpr int AS = 18;

// ---------------------------------------------------------------------------
// Kernel 1: layer-0 bidirectional LSTM, 4-way WARP-UNIFORM K-split.
// block=512: jj = tid&63 (hidden unit), pg = (tid>>6)&1 (8-row group),
// kh = tid>>7 (K quarter, warp-uniform!). Thread accumulates partials over
// kk in [kh*16, kh*16+16) for all 8 rows of its pg group; one-shot smem
// reduction; finishes rows 2kh, 2kh+1. grid=(B/16, 2 dirs) = 128 CTAs.
// ---------------------------------------------------------------------------
static constexpr int RED0_ENT = 2 * 4 * 3 * 2 * 64;            // ulonglong2 entries
static constexpr int SMEM0 = 64 * 256 * 4 + 64 * AS * 8 + RED0_ENT * 16; // 123904

__global__ void __launch_bounds__(512, 1) lstm0_kernel(
    const float* __restrict__ x,
    const float* __restrict__ WihF, const float* __restrict__ WhhF,
    const float* __restrict__ bihF, const float* __restrict__ bhhF,
    const float* __restrict__ WihB, const float* __restrict__ WhhB,
    const float* __restrict__ bihB, const float* __restrict__ bhhB)
{
    extern __shared__ float sm[];
    float*      wt  = sm;                        // [64][256]
    ULL*        h_s = (ULL*)(sm + 64 * 256);     // [64][AS]
    ulonglong2* red = (ulonglong2*)(h_s + 64 * AS);  // [pg][kr][m-1][i][jj]

    const int dir = blockIdx.y;
    const int b0  = blockIdx.x * 16;
    const int tid = threadIdx.x;
    const int jj  = tid & 63;
    const int pg  = (tid >> 6) & 1;
    const int kh  = tid >> 7;            // warp-uniform K quarter

    const float* Wih = dir ? WihB : WihF;
    const float* Whh = dir ? WhhB : WhhF;
    const float* bih = dir ? bihB : bihF;
    const float* bhh = dir ? bhhB : bhhF;

    // stage Whh transposed: wt[kk][j*4+g]
    for (int sidx = tid; sidx < 256 * 64; sidx += 512) {
        int gr = sidx >> 6, kk = sidx & 63;
        wt[kk * 256 + (gr & 63) * 4 + (gr >> 6)] = Whh[sidx];
    }
    ULL wA[3], wB[3];
    #pragma unroll
    for (int c = 0; c < 3; c++) {
        wA[c] = pk2(Wih[jj * 3 + c],         Wih[(64 + jj) * 3 + c]);
        wB[c] = pk2(Wih[(128 + jj) * 3 + c], Wih[(192 + jj) * 3 + c]);
    }
    const ULL biasA = pk2(bih[jj] + bhh[jj],             bih[64 + jj] + bhh[64 + jj]);
    const ULL biasB = pk2(bih[128 + jj] + bhh[128 + jj], bih[192 + jj] + bhh[192 + jj]);

    for (int idx = tid; idx < 64 * AS; idx += 512) h_s[idx] = 0ULL;

    // finishing rows: local r = 2kh, 2kh+1
    const float* xr[2];
    float*       yr[2];
    const int dof = dir ? 64 : 0;
    #pragma unroll
    for (int i = 0; i < 2; i++) {
        int row = 8 * pg + 2 * kh + i;
        xr[i] = x + (size_t)(b0 + row) * 1536;
        yr[i] = g_y0 + (size_t)(b0 + row) * (T * 128) + dof + jj;
    }

    float cs[2] = {0.f, 0.f};
    float hh[2] = {0.f, 0.f};
    const ULL* hp = h_s + pg * 8;
    const int kb = kh * 16;
    __syncthreads();

    for (int s = 0; s < T; s++) {
        const int t = dir ? (T - 1 - s) : s;

        float xv[2][3];
        #pragma unroll
        for (int i = 0; i < 2; i++) {
            xv[i][0] = __ldg(xr[i] + t);
            xv[i][1] = __ldg(xr[i] + 512 + t);
            xv[i][2] = __ldg(xr[i] + 1024 + t);
        }

        ULL A0[8], A1[8];
        #pragma unroll
        for (int r = 0; r < 8; r++) {
            bool own = (r >> 1) == kh;
            A0[r] = own ? biasA : 0ULL;
            A1[r] = own ? biasB : 0ULL;
        }

        #pragma unroll
        for (int kk2 = 0; kk2 < 16; kk2++) {
            int kk = kb + kk2;
            ulonglong2 w2  = *(const ulonglong2*)(wt + kk * 256 + jj * 4);
            ulonglong2 hv0 = *(const ulonglong2*)(hp + kk * AS);
            ulonglong2 hv1 = *(const ulonglong2*)(hp + kk * AS + 2);
            ulonglong2 hv2 = *(const ulonglong2*)(hp + kk * AS + 4);
            ulonglong2 hv3 = *(const ulonglong2*)(hp + kk * AS + 6);
            fma2(A0[0], w2.x, hv0.x);  fma2(A1[0], w2.y, hv0.x);
            fma2(A0[1], w2.x, hv0.y);  fma2(A1[1], w2.y, hv0.y);
            fma2(A0[2], w2.x, hv1.x);  fma2(A1[2], w2.y, hv1.x);
            fma2(A0[3], w2.x, hv1.y);  fma2(A1[3], w2.y, hv1.y);
            fma2(A0[4], w2.x, hv2.x);  fma2(A1[4], w2.y, hv2.x);
            fma2(A0[5], w2.x, hv2.y);  fma2(A1[5], w2.y, hv2.y);
            fma2(A0[6], w2.x, hv3.x);  fma2(A1[6], w2.y, hv3.x);
            fma2(A0[7], w2.x, hv3.y);  fma2(A1[7], w2.y, hv3.y);
        }
        __syncthreads();   // B: all h_s reads done

        // one-shot reduction write: for each non-owned row r, write partial to
        // receiver kr=r>>1, slot m-1 (m = kh^kr). Register indices constant.
        #pragma unroll
        for (int r = 0; r < 8; r++) {
            int kr = r >> 1, i = r & 1;
            int m = kh ^ kr;
            if (m != 0)
                red[(((pg * 4 + kr) * 3 + (m - 1)) * 2 + i) * 64 + jj]
                    = make_ulonglong2(A0[r], A1[r]);
        }
        __syncthreads();   // C: partials visible

        ULL B0[2], B1[2];
        #pragma unroll
        for (int r = 0; r < 8; r++) {
            if ((r >> 1) == kh) { B0[r & 1] = A0[r]; B1[r & 1] = A1[r]; }
        }
        #pragma unroll
        for (int m = 1; m <= 3; m++) {
            #pragma unroll
            for (int i = 0; i < 2; i++) {
                ulonglong2 q = red[(((pg * 4 + kh) * 3 + (m - 1)) * 2 + i) * 64 + jj];
                add2(B0[i], q.x);
                add2(B1[i], q.y);
            }
        }

        // finish: x terms + activations + state update for 2 rows
        #pragma unroll
        for (int i = 0; i < 2; i++) {
            #pragma unroll
            for (int c = 0; c < 3; c++) {
                ULL xd = dup2(xv[i][c]);
                fma2(B0[i], wA[c], xd);
                fma2(B1[i], wB[c], xd);
            }
            float ai, af, ag, ao;
            unpk(B0[i], ai, af);
            unpk(B1[i], ag, ao);
            cs[i] = sig_f(af) * cs[i] + sig_f(ai) * tanh_f(ag);
            hh[i] = sig_f(ao) * tanh_f(cs[i]);
            yr[i][(size_t)t * 128] = hh[i];
        }

        // publish h (dup-packed) for next step
        *(ulonglong2*)(h_s + jj * AS + pg * 8 + 2 * kh)
            = make_ulonglong2(dup2(hh[0]), dup2(hh[1]));
        __syncthreads();   // D: h(t+1) visible
    }
}

// ---------------------------------------------------------------------------
// Kernel 2: layer-1 bidirectional LSTM, input GEMM fused, 4-way K-split.
// Same tid map. Combined act[0..127]=y0(t), act[128..191]=h (dup'd);
// wt[0..127]=Wih1^T, wt[128..191]=Whh1^T. kh covers kk in [kh*48, kh*48+48).
// Reduction: 3 ping-rounds through a 16KB buffer aliased on the y-region
// (dead between barriers B and D). grid=(B/16, 2) = 128 CTAs.
// ---------------------------------------------------------------------------
static constexpr int SMEM1 = 192 * 256 * 4 + 192 * AS * 8;  // 224256

__global__ void __launch_bounds__(512, 1) lstm1_kernel(
    const float* __restrict__ WihF, const float* __restrict__ WhhF,
    const float* __restrict__ bihF, const float* __restrict__ bhhF,
    const float* __restrict__ WihB, const float* __restrict__ WhhB,
    const float* __restrict__ bihB, const float* __restrict__ bhhB)
{
    extern __shared__ float sm[];
    float*      wt  = sm;                          // [192][256]
    ULL*        act = (ULL*)(sm + 192 * 256);      // [192][AS]: y then h
    ULL*        h_s = act + 128 * AS;
    ulonglong2* red = (ulonglong2*)act;            // [pg][kr][i][jj] = 16KB <= y region

    const int dir = blockIdx.y;
    const int b0  = blockIdx.x * 16;
    const int tid = threadIdx.x;
    const int jj  = tid & 63;
    const int pg  = (tid >> 6) & 1;
    const int kh  = tid >> 7;            // warp-uniform K quarter

    const float* Wih = dir ? WihB : WihF;
    const float* Whh = dir ? WhhB : WhhF;
    const float* bih = dir ? bihB : bihF;
    const float* bhh = dir ? bhhB : bhhF;

    for (int sidx = tid; sidx < 256 * 128; sidx += 512) {
        int gr = sidx >> 7, kk = sidx & 127;
        wt[kk * 256 + (gr & 63) * 4 + (gr >> 6)] = Wih[sidx];
    }
    for (int sidx = tid; sidx < 256 * 64; sidx += 512) {
        int gr = sidx >> 6, kk = sidx & 63;
        wt[(128 + kk) * 256 + (gr & 63) * 4 + (gr >> 6)] = Whh[sidx];
    }
    const ULL biasA = pk2(bih[jj] + bhh[jj],             bih[64 + jj] + bhh[64 + jj]);
    const ULL biasB = pk2(bih[128 + jj] + bhh[128 + jj], bih[192 + jj] + bhh[192 + jj]);

    for (int idx = tid; idx < 64 * AS; idx += 512) h_s[idx] = 0ULL;

    // y-fill role: row frow = tid>>5 (0..15), feats (tid&31) + 32*i, i<4
    const int frow = tid >> 5;
    const int flo  = tid & 31;
    const float* ybase = g_y0 + (size_t)(b0 + frow) * (T * 128) + flo;

    float cs[2] = {0.f, 0.f};
    float hh[2] = {0.f, 0.f};
    const ULL* ap = act + pg * 8;
    const int kb = kh * 48;
    const int dof = dir ? 64 : 0;

    // prefetch first step's y0
    float p[4];
    {
        int t0 = dir ? T - 1 : 0;
        #pragma unroll
        for (int i = 0; i < 4; i++)
            p[i] = ybase[(size_t)t0 * 128 + 32 * i];
    }
    __syncthreads();

    for (int s = 0; s < T; s++) {
        // publish this step's y0 (dup-packed) into act[0..127]
        #pragma unroll
        for (int i = 0; i < 4; i++)
            act[(32 * i + flo) * AS + frow] = dup2(p[i]);
        __syncthreads();   // A: y + h visible

        // prefetch next step's y0 (hidden under the K-loop)
        if (s + 1 < T) {
            int tn = dir ? (T - 2 - s) : (s + 1);
            #pragma unroll
            for (int i = 0; i < 4; i++)
                p[i] = ybase[(size_t)tn * 128 + 32 * i];
        }

        ULL A0[8], A1[8];
        #pragma unroll
        for (int r = 0; r < 8; r++) {
            bool own = (r >> 1) == kh;
            A0[r] = own ? biasA : 0ULL;
            A1[r] = own ? biasB : 0ULL;
        }

        #pragma unroll 8
        for (int kk2 = 0; kk2 < 48; kk2++) {
            int kk = kb + kk2;
            ulonglong2 w2  = *(const ulonglong2*)(wt + kk * 256 + jj * 4);
            ulonglong2 av0 = *(const ulonglong2*)(ap + kk * AS);
            ulonglong2 av1 = *(const ulonglong2*)(ap + kk * AS + 2);
            ulonglong2 av2 = *(const ulonglong2*)(ap + kk * AS + 4);
            ulonglong2 av3 = *(const ulonglong2*)(ap + kk * AS + 6);
            fma2(A0[0], w2.x, av0.x);  fma2(A1[0], w2.y, av0.x);
            fma2(A0[1], w2.x, av0.y);  fma2(A1[1], w2.y, av0.y);
            fma2(A0[2], w2.x, av1.x);  fma2(A1[2], w2.y, av1.x);
            fma2(A0[3], w2.x, av1.y);  fma2(A1[3], w2.y, av1.y);
            fma2(A0[4], w2.x, av2.x);  fma2(A1[4], w2.y, av2.x);
            fma2(A0[5], w2.x, av2.y);  fma2(A1[5], w2.y, av2.y);
            fma2(A0[6], w2.x, av3.x);  fma2(A1[6], w2.y, av3.x);
            fma2(A0[7], w2.x, av3.y);  fma2(A1[7], w2.y, av3.y);
        }
        __syncthreads();   // B: all act reads done -> y region reusable as red

        ULL B0[2], B1[2];
        #pragma unroll
        for (int r = 0; r < 8; r++) {
            if ((r >> 1) == kh) { B0[r & 1] = A0[r]; B1[r & 1] = A1[r]; }
        }

        // 3 ping-rounds through the 16KB aliased buffer
        #pragma unroll
        for (int m = 1; m <= 3; m++) {
            #pragma unroll
            for (int r = 0; r < 8; r++) {
                if ((r >> 1) == (kh ^ m))   // rows owned by my receiver this round
                    red[((pg * 4 + (r >> 1)) * 2 + (r & 1)) * 64 + jj]
                        = make_ulonglong2(A0[r], A1[r]);
            }
            __syncthreads();               // partials visible
            #pragma unroll
            for (int i = 0; i < 2; i++) {
                ulonglong2 q = red[((pg * 4 + kh) * 2 + i) * 64 + jj];
                add2(B0[i], q.x);
                add2(B1[i], q.y);
            }
            if (m < 3) __syncthreads();    // reads done before next round's writes
        }

        #pragma unroll
        for (int i = 0; i < 2; i++) {
            float ai, af, ag, ao;
            unpk(B0[i], ai, af);
            unpk(B1[i], ag, ao);
            cs[i] = sig_f(af) * cs[i] + sig_f(ai) * tanh_f(ag);
            hh[i] = sig_f(ao) * tanh_f(cs[i]);
        }

        // publish h (dup-packed)
        *(ulonglong2*)(h_s + jj * AS + pg * 8 + 2 * kh)
            = make_ulonglong2(dup2(hh[0]), dup2(hh[1]));
        __syncthreads();   // D: h visible, red reads done before next y publish
    }

    #pragma unroll
    for (int i = 0; i < 2; i++) {
        int row = 8 * pg + 2 * kh + i;
        g_hcat[(size_t)(b0 + row) * 128 + dof + jj] = hh[i];
    }
}

// ---------------------------------------------------------------------------
// Kernel 3: FC head. block = 256 = 4 rows x 64 fc1-outputs, grid = B/4.
// ---------------------------------------------------------------------------
__global__ void __launch_bounds__(256) head_kernel(
    const float* __restrict__ fc1W, const float* __restrict__ fc1b,
    const float* __restrict__ fc2W, const float* __restrict__ fc2b,
    float* __restrict__ out)
{
    __shared__ float f1[4][64];
    const int j = threadIdx.x;
    const int r = j >> 6;
    const int o = j & 63;
    const int b = blockIdx.x * 4 + r;

    const float* h = g_hcat + (size_t)b * 128;
    const float* w = fc1W + o * 128;
    float acc = fc1b[o];
    #pragma unroll 8
    for (int kk = 0; kk < 128; kk++) acc += w[kk] * h[kk];
    f1[r][o] = fmaxf(acc, 0.0f);
    __syncthreads();

    if (o < 2) {
        float a = fc2b[o];
        const float* w2 = fc2W + o * 64;
        #pragma unroll 8
        for (int kk = 0; kk < 64; kk++) a += w2[kk] * f1[r][kk];
        out[(size_t)b * 2 + o] = a;
    }
}

// ---------------------------------------------------------------------------
// Launcher
// ---------------------------------------------------------------------------
extern "C" void kernel_launch(void* const* d_in, const int* in_sizes, int n_in,
                              void* d_out, int out_size)
{
    const float* x      = (const float*)d_in[0];
    const float* Wih0f  = (const float*)d_in[1];
    const float* Whh0f  = (const float*)d_in[2];
    const float* bih0f  = (const float*)d_in[3];
    const float* bhh0f  = (const float*)d_in[4];
    const float* Wih0b  = (const float*)d_in[5];
    const float* Whh0b  = (const float*)d_in[6];
    const float* bih0b  = (const float*)d_in[7];
    const float* bhh0b  = (const float*)d_in[8];
    const float* Wih1f  = (const float*)d_in[9];
    const float* Whh1f  = (const float*)d_in[10];
    const float* bih1f  = (const float*)d_in[11];
    const float* bhh1f  = (const float*)d_in[12];
    const float* Wih1b  = (const float*)d_in[13];
    const float* Whh1b  = (const float*)d_in[14];
    const float* bih1b  = (const float*)d_in[15];
    const float* bhh1b  = (const float*)d_in[16];
    const float* fc1W   = (const float*)d_in[17];
    const float* fc1b   = (const float*)d_in[18];
    const float* fc2W   = (const float*)d_in[19];
    const float* fc2b   = (const float*)d_in[20];
    float* out = (float*)d_out;

    cudaFuncSetAttribute(lstm0_kernel,
                         cudaFuncAttributeMaxDynamicSharedMemorySize, SMEM0);
    cudaFuncSetAttribute(lstm1_kernel,
                         cudaFuncAttributeMaxDynamicSharedMemorySize, SMEM1);

    dim3 grid(B / 16, 2);
    lstm0_kernel<<<grid, 512, SMEM0>>>(x,
                                       Wih0f, Whh0f, bih0f, bhh0f,
                                       Wih0b, Whh0b, bih0b, bhh0b);

    lstm1_kernel<<<grid, 512, SMEM1>>>(Wih1f, Whh1f, bih1f, bhh1f,
                                       Wih1b, Whh1b, bih1b, bhh1b);

    head_kernel<<<B / 4, 256>>>(fc1W, fc1b, fc2W, fc2b, out);
}